// round 11
// baseline (speedup 1.0000x reference)
#include <cuda_runtime.h>
#include <cuda_bf16.h>

#define BLK        256
#define NWARP      (BLK / 32)
#define GRID       456                   // 3 blocks/SM x 152 SMs -> single persistent wave
#define WROWS      16                    // rows per warp
#define TILE_ROWS  (NWARP * WROWS)       // 128 rows per block
#define CHUNK      20                    // time-steps per chunk (100 = 5 x 20, no tail)
#define C4MAX      5                     // float4 per row per chunk
#define S4         5                     // float4 row stride in smem
#define NSLOT      3
#define WBUF_F4    (WROWS * S4)          // 80 float4 per (slot, array, warp)
#define SMEM_BYTES (NSLOT * 2 * NWARP * WBUF_F4 * 16)   // 61440 B -> 3 blocks/SM

// Scratch (alloc-free rule). g_tick wraps to 0 every launch -> graph-replay safe.
__device__ float g_partials[GRID];
__device__ unsigned int g_tick;

__device__ __forceinline__ void cp16(unsigned s, const void* g) {
    asm volatile("cp.async.cg.shared.global [%0], [%1], 16;" :: "r"(s), "l"(g));
}
__device__ __forceinline__ void cp_commit() {
    asm volatile("cp.async.commit_group;");
}
template <int N> __device__ __forceinline__ void cp_wait() {
    asm volatile("cp.async.wait_group %0;" :: "n"(N));
}

__global__ void __launch_bounds__(BLK) spike_loss_kernel(
    const float* __restrict__ outputs,
    const float* __restrict__ target,
    const int* __restrict__ n_steps_p,
    const int* __restrict__ tau_p,
    long long total_elems,
    float* __restrict__ out)
{
    extern __shared__ float4 sm[];

    const int   T       = *n_steps_p;
    const float inv_tau = 1.0f / (float)(*tau_p);
    const float decay   = 1.0f - inv_tau;
    const long long rows = (T > 0) ? total_elems / (long long)T : 0;

    const int tid  = threadIdx.x;
    const int wid  = tid >> 5;
    const int lane = tid & 31;
    float acc = 0.0f;

    if (T >= 4 && (T & 3) == 0) {
        // ===== fast path: 24 warps/SM, per-warp 3-slot cp.async pipelines =====
        const unsigned sm_base = (unsigned)__cvta_generic_to_shared(sm);
        const int nch   = (T + CHUNK - 1) / CHUNK;
        const int last4 = (T - (nch - 1) * CHUNK + 3) >> 2;   // f4s in last chunk (1..5)

        const long long wrow_base   = (long long)blockIdx.x * TILE_ROWS + wid * WROWS;
        const long long tile_stride = (long long)GRID * TILE_ROWS;

        long long ntiles = 0;
        {
            const long long first = (long long)blockIdx.x * TILE_ROWS;
            if (first < rows)
                ntiles = (rows - first + tile_stride - 1) / tile_stride;
        }
        const long long nci = ntiles * nch;

        // smem base (float4 units) for (slot, arr) of this warp
        auto buf_f4 = [&](int slot, int arr) -> unsigned {
            return (unsigned)(((slot * 2 + arr) * NWARP + wid) * WBUF_F4);
        };

        // stage flat-chunk ci: 16 rows x c4 f4 x 2 arrays, combined index space
        auto load_chunk = [&](long long ci, int slot) {
            const long long row0 = wrow_base + (ci / nch) * tile_stride;
            const int k  = (int)(ci % nch);
            const int t0 = k * CHUNK;
            const int c4 = (k == nch - 1) ? last4 : C4MAX;
            const unsigned st = sm_base + buf_f4(slot, 0) * 16;
            const unsigned so = sm_base + buf_f4(slot, 1) * 16;
            if (c4 == C4MAX) {
                #pragma unroll
                for (int it = 0; it < C4MAX; ++it) {          // 160 f4 / 32 lanes
                    const int fid = it * 32 + lane;           // 0..159
                    const int arr = (fid >= WROWS * C4MAX);
                    const int fl  = fid - arr * (WROWS * C4MAX);
                    const int r = fl / C4MAX, j = fl - r * C4MAX;
                    const long long row = row0 + r;
                    if (row < rows) {
                        const long long g = row * (long long)T + t0 + 4 * j;
                        const unsigned off = (unsigned)((r * S4 + j) * 16);
                        if (arr) cp16(so + off, outputs + g);
                        else     cp16(st + off, target  + g);
                    }
                }
            } else {
                for (int fid = lane; fid < 2 * WROWS * c4; fid += 32) {
                    const int arr = (fid >= WROWS * c4);
                    const int fl  = fid - arr * (WROWS * c4);
                    const int r = fl / c4, j = fl - r * c4;
                    const long long row = row0 + r;
                    if (row < rows) {
                        const long long g = row * (long long)T + t0 + 4 * j;
                        const unsigned off = (unsigned)((r * S4 + j) * 16);
                        if (arr) cp16(so + off, outputs + g);
                        else     cp16(st + off, target  + g);
                    }
                }
            }
            cp_commit();
        };

        // prologue (per warp)
        if (nci > 0) load_chunk(0, 0);
        if (nci > 1) load_chunk(1, 1);

        float syn = 0.0f;
        int slot = 0;

        for (long long ci = 0; ci < nci; ++ci) {
            if (ci + 1 < nci) cp_wait<1>(); else cp_wait<0>();
            __syncwarp();        // all lanes past compute of ci-1; slot (ci+2)%3 free

            // issue next load BEFORE compute
            if (ci + 2 < nci) {
                int nslot = slot + 2; if (nslot >= NSLOT) nslot -= NSLOT;
                load_chunk(ci + 2, nslot);
            }

            const long long row0 = wrow_base + (ci / nch) * tile_stride;
            const int k  = (int)(ci % nch);
            const int c4 = (k == nch - 1) ? last4 : C4MAX;
            if (k == 0) syn = 0.0f;

            if (lane < WROWS && row0 + lane < rows) {
                const float4* xt = sm + buf_f4(slot, 0) + lane * S4;
                const float4* xo = sm + buf_f4(slot, 1) + lane * S4;
                if (c4 == C4MAX) {
                    #pragma unroll
                    for (int j = 0; j < C4MAX; ++j) {
                        const float4 x = xt[j];
                        const float4 o = xo[j];
                        float e;
                        syn = fmaf(syn, decay, x.x); e = fmaf(-syn, inv_tau, o.x); acc = fmaf(e, e, acc);
                        syn = fmaf(syn, decay, x.y); e = fmaf(-syn, inv_tau, o.y); acc = fmaf(e, e, acc);
                        syn = fmaf(syn, decay, x.z); e = fmaf(-syn, inv_tau, o.z); acc = fmaf(e, e, acc);
                        syn = fmaf(syn, decay, x.w); e = fmaf(-syn, inv_tau, o.w); acc = fmaf(e, e, acc);
                    }
                } else {
                    for (int j = 0; j < c4; ++j) {
                        const float4 x = xt[j];
                        const float4 o = xo[j];
                        float e;
                        syn = fmaf(syn, decay, x.x); e = fmaf(-syn, inv_tau, o.x); acc = fmaf(e, e, acc);
                        syn = fmaf(syn, decay, x.y); e = fmaf(-syn, inv_tau, o.y); acc = fmaf(e, e, acc);
                        syn = fmaf(syn, decay, x.z); e = fmaf(-syn, inv_tau, o.z); acc = fmaf(e, e, acc);
                        syn = fmaf(syn, decay, x.w); e = fmaf(-syn, inv_tau, o.w); acc = fmaf(e, e, acc);
                    }
                }
            }
            if (++slot >= NSLOT) slot = 0;
        }
    } else if (T > 0) {
        // ===== generic fallback: scalar thread-per-row =====
        const long long gtid = (long long)blockIdx.x * BLK + tid;
        for (long long row = gtid; row < rows; row += (long long)GRID * BLK) {
            const float* tg = target  + row * (long long)T;
            const float* op = outputs + row * (long long)T;
            float syn = 0.0f;
            for (int t = 0; t < T; ++t) {
                syn = fmaf(syn, decay, tg[t]);
                const float e = fmaf(-syn, inv_tau, op[t]);
                acc = fmaf(e, e, acc);
            }
        }
    }

    // ---- block reduce ----
    #pragma unroll
    for (int off = 16; off > 0; off >>= 1)
        acc += __shfl_xor_sync(0xFFFFFFFF, acc, off);

    __shared__ float wsum[NWARP];
    if (lane == 0) wsum[wid] = acc;
    __syncthreads();

    __shared__ bool is_last;
    if (tid == 0) {
        float s = 0.0f;
        #pragma unroll
        for (int i = 0; i < NWARP; ++i) s += wsum[i];
        g_partials[blockIdx.x] = s;
        __threadfence();
        const unsigned prev = atomicInc(&g_tick, GRID - 1);   // wraps to 0 each launch
        is_last = (prev == GRID - 1);
    }
    __syncthreads();

    if (is_last) {
        double d = 0.0;
        for (int i = tid; i < GRID; i += BLK)
            d += (double)g_partials[i];
        #pragma unroll
        for (int off = 16; off > 0; off >>= 1)
            d += __shfl_xor_sync(0xFFFFFFFF, d, off);
        __shared__ double dsum[NWARP];
        if (lane == 0) dsum[wid] = d;
        __syncthreads();
        if (tid == 0) {
            double t = 0.0;
            #pragma unroll
            for (int i = 0; i < NWARP; ++i) t += dsum[i];
            out[0] = (float)(0.5 * t);
        }
    }
}

extern "C" void kernel_launch(void* const* d_in, const int* in_sizes, int n_in,
                              void* d_out, int out_size)
{
    const float* outputs = (const float*)d_in[0];
    const float* target  = (const float*)d_in[1];
    const int*   n_steps = (const int*)d_in[2];
    const int*   tau_s   = (const int*)d_in[3];
    float*       out     = (float*)d_out;

    const long long total = (long long)in_sizes[0];

    cudaFuncSetAttribute(spike_loss_kernel,
                         cudaFuncAttributeMaxDynamicSharedMemorySize, SMEM_BYTES);
    spike_loss_kernel<<<GRID, BLK, SMEM_BYTES>>>(outputs, target, n_steps, tau_s, total, out);
}

// round 12
// speedup vs baseline: 1.1166x; 1.1166x over previous
#include <cuda_runtime.h>
#include <cuda_bf16.h>

#define BLK        128
#define NWARP      4
#define GRID       152                    // 1 block/SM, persistent
#define WROWS      32                     // rows per group (contiguous 32*T floats)
#define NSLOT      2
#define SLOT_BYTES 12800                  // per array: 32 rows x up to 100 f32
#define SLOT_FLOATS (SLOT_BYTES / 4)
#define SMEM_BYTES (NWARP * NSLOT * 2 * SLOT_BYTES)   // 204800 B

// Scratch (alloc-free rule). g_tick wraps to 0 every launch -> graph-replay safe.
__device__ float g_partials[GRID];
__device__ unsigned int g_tick;

__device__ __forceinline__ void mbar_init(unsigned addr, unsigned count) {
    asm volatile("mbarrier.init.shared.b64 [%0], %1;" :: "r"(addr), "r"(count) : "memory");
}
__device__ __forceinline__ void mbar_expect_tx(unsigned addr, unsigned bytes) {
    asm volatile("mbarrier.arrive.expect_tx.shared.b64 _, [%0], %1;"
                 :: "r"(addr), "r"(bytes) : "memory");
}
__device__ __forceinline__ void bulk_g2s(unsigned dst, const void* src,
                                         unsigned bytes, unsigned mbar) {
    asm volatile("cp.async.bulk.shared::cta.global.mbarrier::complete_tx::bytes "
                 "[%0], [%1], %2, [%3];"
                 :: "r"(dst), "l"(src), "r"(bytes), "r"(mbar) : "memory");
}
__device__ __forceinline__ void mbar_wait(unsigned addr, unsigned parity) {
    asm volatile(
        "{\n\t"
        ".reg .pred P;\n\t"
        "WAIT_%=:\n\t"
        "mbarrier.try_wait.parity.acquire.cta.shared::cta.b64 P, [%0], %1, 0x989680;\n\t"
        "@P bra.uni DONE_%=;\n\t"
        "bra.uni WAIT_%=;\n\t"
        "DONE_%=:\n\t"
        "}"
        :: "r"(addr), "r"(parity) : "memory");
}

__global__ void __launch_bounds__(BLK) spike_loss_kernel(
    const float* __restrict__ outputs,
    const float* __restrict__ target,
    const int* __restrict__ n_steps_p,
    const int* __restrict__ tau_p,
    long long total_elems,
    float* __restrict__ out)
{
    extern __shared__ float smem[];
    __shared__ alignas(8) unsigned long long mbar_store[NWARP][NSLOT];

    const int   T       = *n_steps_p;
    const float inv_tau = 1.0f / (float)(*tau_p);
    const float decay   = 1.0f - inv_tau;
    const long long rows = (T > 0) ? total_elems / (long long)T : 0;

    const int tid  = threadIdx.x;
    const int wid  = tid >> 5;
    const int lane = tid & 31;
    float acc = 0.0f;

    const bool fast = (T >= 4) && ((T & 3) == 0) && (WROWS * T * 4 <= SLOT_BYTES);

    long long fast_rows = 0;

    if (fast) {
        // ===== fast path: per-warp bulk-copy pipeline over 32-row groups =====
        const unsigned sm_base   = (unsigned)__cvta_generic_to_shared(smem);
        const unsigned mbar_base = (unsigned)__cvta_generic_to_shared(&mbar_store[0][0]);

        if (tid == 0) {
            #pragma unroll
            for (int i = 0; i < NWARP * NSLOT; ++i)
                mbar_init(mbar_base + 8u * i, 1);
        }
        __syncthreads();

        const long long ngroups  = rows / WROWS;
        fast_rows = ngroups * WROWS;
        const int  nstreams = GRID * NWARP;
        const int  sid      = blockIdx.x * NWARP + wid;
        long long n_ci = 0;
        if ((long long)sid < ngroups)
            n_ci = (ngroups - sid + nstreams - 1) / nstreams;

        const unsigned bytes_arr = (unsigned)(WROWS * T * 4);
        const int T4 = T >> 2;

        // float offsets of this warp's (slot, array) buffers
        auto slot_f = [&](int s, int a) -> unsigned {
            return (unsigned)(((wid * NSLOT + s) * 2 + a) * SLOT_FLOATS);
        };
        auto mb_addr = [&](int s) -> unsigned {
            return mbar_base + 8u * (unsigned)(wid * NSLOT + s);
        };

        auto issue = [&](long long ci) {
            const int s = (int)(ci & 1);
            const long long g = (long long)sid + ci * nstreams;
            const long long e0 = g * (long long)WROWS * T;
            if (lane == 0) {
                const unsigned mb = mb_addr(s);
                mbar_expect_tx(mb, 2 * bytes_arr);
                bulk_g2s(sm_base + slot_f(s, 0) * 4, target  + e0, bytes_arr, mb);
                bulk_g2s(sm_base + slot_f(s, 1) * 4, outputs + e0, bytes_arr, mb);
            }
        };

        if (n_ci > 0) issue(0);
        if (n_ci > 1) issue(1);

        for (long long ci = 0; ci < n_ci; ++ci) {
            const int s = (int)(ci & 1);
            mbar_wait(mb_addr(s), (unsigned)((ci >> 1) & 1));

            // lane = row within group; stride T floats (conflict-free phases for T%8==4)
            const float4* xt = (const float4*)(smem + slot_f(s, 0) + lane * T);
            const float4* xo = (const float4*)(smem + slot_f(s, 1) + lane * T);
            float syn = 0.0f;
            #pragma unroll 5
            for (int j = 0; j < T4; ++j) {
                const float4 x = xt[j];
                const float4 o = xo[j];
                float e;
                syn = fmaf(syn, decay, x.x); e = fmaf(-syn, inv_tau, o.x); acc = fmaf(e, e, acc);
                syn = fmaf(syn, decay, x.y); e = fmaf(-syn, inv_tau, o.y); acc = fmaf(e, e, acc);
                syn = fmaf(syn, decay, x.z); e = fmaf(-syn, inv_tau, o.z); acc = fmaf(e, e, acc);
                syn = fmaf(syn, decay, x.w); e = fmaf(-syn, inv_tau, o.w); acc = fmaf(e, e, acc);
            }

            __syncwarp();                       // all lanes done reading slot s
            if (ci + 2 < n_ci) issue(ci + 2);   // refill the slot just vacated
        }
    }

    // ===== tail / generic path: scalar thread-per-row from global =====
    if (T > 0) {
        for (long long row = fast_rows + (long long)blockIdx.x * BLK + tid;
             row < rows; row += (long long)GRID * BLK) {
            const float* tg = target  + row * (long long)T;
            const float* op = outputs + row * (long long)T;
            float syn = 0.0f;
            for (int t = 0; t < T; ++t) {
                syn = fmaf(syn, decay, tg[t]);
                const float e = fmaf(-syn, inv_tau, op[t]);
                acc = fmaf(e, e, acc);
            }
        }
    }

    // ---- block reduce ----
    #pragma unroll
    for (int off = 16; off > 0; off >>= 1)
        acc += __shfl_xor_sync(0xFFFFFFFF, acc, off);

    __shared__ float wsum[NWARP];
    if (lane == 0) wsum[wid] = acc;
    __syncthreads();

    __shared__ bool is_last;
    if (tid == 0) {
        float s = 0.0f;
        #pragma unroll
        for (int i = 0; i < NWARP; ++i) s += wsum[i];
        g_partials[blockIdx.x] = s;
        __threadfence();
        const unsigned prev = atomicInc(&g_tick, GRID - 1);   // wraps to 0 each launch
        is_last = (prev == GRID - 1);
    }
    __syncthreads();

    if (is_last) {
        double d = 0.0;
        for (int i = tid; i < GRID; i += BLK)
            d += (double)g_partials[i];
        #pragma unroll
        for (int off = 16; off > 0; off >>= 1)
            d += __shfl_xor_sync(0xFFFFFFFF, d, off);
        __shared__ double dsum[NWARP];
        if (lane == 0) dsum[wid] = d;
        __syncthreads();
        if (tid == 0) {
            double t = 0.0;
            #pragma unroll
            for (int i = 0; i < NWARP; ++i) t += dsum[i];
            out[0] = (float)(0.5 * t);
        }
    }
}

extern "C" void kernel_launch(void* const* d_in, const int* in_sizes, int n_in,
                              void* d_out, int out_size)
{
    const float* outputs = (const float*)d_in[0];
    const float* target  = (const float*)d_in[1];
    const int*   n_steps = (const int*)d_in[2];
    const int*   tau_s   = (const int*)d_in[3];
    float*       out     = (float*)d_out;

    const long long total = (long long)in_sizes[0];

    cudaFuncSetAttribute(spike_loss_kernel,
                         cudaFuncAttributeMaxDynamicSharedMemorySize, SMEM_BYTES);
    spike_loss_kernel<<<GRID, BLK, SMEM_BYTES>>>(outputs, target, n_steps, tau_s, total, out);
}

// round 13
// speedup vs baseline: 1.1203x; 1.0033x over previous
#include <cuda_runtime.h>
#include <cuda_bf16.h>

#define BLK        256
#define NWARP      8
#define GRID       152                    // 1 block/SM, persistent
#define WROWS      16                     // rows per group (contiguous WROWS*T floats)
#define NSLOT      2
#define SLOT_BYTES 6400                   // per array: 16 rows x up to 100 f32
#define SLOT_FLOATS (SLOT_BYTES / 4)
#define SMEM_BYTES (NWARP * NSLOT * 2 * SLOT_BYTES)   // 204800 B -> 1 block/SM

// Scratch (alloc-free rule). g_tick wraps to 0 every launch -> graph-replay safe.
__device__ float g_partials[GRID];
__device__ unsigned int g_tick;

__device__ __forceinline__ void mbar_init(unsigned addr, unsigned count) {
    asm volatile("mbarrier.init.shared.b64 [%0], %1;" :: "r"(addr), "r"(count) : "memory");
}
__device__ __forceinline__ void mbar_expect_tx(unsigned addr, unsigned bytes) {
    asm volatile("mbarrier.arrive.expect_tx.shared.b64 _, [%0], %1;"
                 :: "r"(addr), "r"(bytes) : "memory");
}
__device__ __forceinline__ void bulk_g2s(unsigned dst, const void* src,
                                         unsigned bytes, unsigned mbar) {
    asm volatile("cp.async.bulk.shared::cta.global.mbarrier::complete_tx::bytes "
                 "[%0], [%1], %2, [%3];"
                 :: "r"(dst), "l"(src), "r"(bytes), "r"(mbar) : "memory");
}
__device__ __forceinline__ void mbar_wait(unsigned addr, unsigned parity) {
    asm volatile(
        "{\n\t"
        ".reg .pred P;\n\t"
        "WAIT_%=:\n\t"
        "mbarrier.try_wait.parity.acquire.cta.shared::cta.b64 P, [%0], %1, 0x989680;\n\t"
        "@P bra.uni DONE_%=;\n\t"
        "bra.uni WAIT_%=;\n\t"
        "DONE_%=:\n\t"
        "}"
        :: "r"(addr), "r"(parity) : "memory");
}

__global__ void __launch_bounds__(BLK) spike_loss_kernel(
    const float* __restrict__ outputs,
    const float* __restrict__ target,
    const int* __restrict__ n_steps_p,
    const int* __restrict__ tau_p,
    long long total_elems,
    float* __restrict__ out)
{
    extern __shared__ float smem[];
    __shared__ alignas(8) unsigned long long mbar_store[NWARP][NSLOT];

    const int   T       = *n_steps_p;
    const float inv_tau = 1.0f / (float)(*tau_p);
    const float decay   = 1.0f - inv_tau;
    const long long rows = (T > 0) ? total_elems / (long long)T : 0;

    const int tid  = threadIdx.x;
    const int wid  = tid >> 5;
    const int lane = tid & 31;
    float acc = 0.0f;

    const bool fast = (T >= 4) && ((T & 3) == 0) && (WROWS * T * 4 <= SLOT_BYTES);

    long long fast_rows = 0;

    if (fast) {
        // ===== fast path: per-warp bulk-copy pipeline over 16-row groups =====
        const unsigned sm_base   = (unsigned)__cvta_generic_to_shared(smem);
        const unsigned mbar_base = (unsigned)__cvta_generic_to_shared(&mbar_store[0][0]);

        if (tid == 0) {
            #pragma unroll
            for (int i = 0; i < NWARP * NSLOT; ++i)
                mbar_init(mbar_base + 8u * i, 1);
        }
        __syncthreads();

        const long long ngroups  = rows / WROWS;
        fast_rows = ngroups * WROWS;
        const int  nstreams = GRID * NWARP;            // 1216 independent streams
        const int  sid      = blockIdx.x * NWARP + wid;
        long long n_ci = 0;
        if ((long long)sid < ngroups)
            n_ci = (ngroups - sid + nstreams - 1) / nstreams;

        const unsigned bytes_arr = (unsigned)(WROWS * T * 4);
        const int T4 = T >> 2;

        auto slot_f = [&](int s, int a) -> unsigned {
            return (unsigned)(((wid * NSLOT + s) * 2 + a) * SLOT_FLOATS);
        };
        auto mb_addr = [&](int s) -> unsigned {
            return mbar_base + 8u * (unsigned)(wid * NSLOT + s);
        };

        auto issue = [&](long long ci) {
            const int s = (int)(ci & 1);
            const long long g = (long long)sid + ci * nstreams;
            const long long e0 = g * (long long)WROWS * T;
            if (lane == 0) {
                const unsigned mb = mb_addr(s);
                mbar_expect_tx(mb, 2 * bytes_arr);
                bulk_g2s(sm_base + slot_f(s, 0) * 4, target  + e0, bytes_arr, mb);
                bulk_g2s(sm_base + slot_f(s, 1) * 4, outputs + e0, bytes_arr, mb);
            }
        };

        if (n_ci > 0) issue(0);
        if (n_ci > 1) issue(1);

        for (long long ci = 0; ci < n_ci; ++ci) {
            const int s = (int)(ci & 1);
            mbar_wait(mb_addr(s), (unsigned)((ci >> 1) & 1));

            if (lane < WROWS) {
                // lane = row within group; stride T floats (conflict-free for T%8==4)
                const float4* xt = (const float4*)(smem + slot_f(s, 0) + lane * T);
                const float4* xo = (const float4*)(smem + slot_f(s, 1) + lane * T);
                float syn = 0.0f;
                #pragma unroll 5
                for (int j = 0; j < T4; ++j) {
                    const float4 x = xt[j];
                    const float4 o = xo[j];
                    float e;
                    syn = fmaf(syn, decay, x.x); e = fmaf(-syn, inv_tau, o.x); acc = fmaf(e, e, acc);
                    syn = fmaf(syn, decay, x.y); e = fmaf(-syn, inv_tau, o.y); acc = fmaf(e, e, acc);
                    syn = fmaf(syn, decay, x.z); e = fmaf(-syn, inv_tau, o.z); acc = fmaf(e, e, acc);
                    syn = fmaf(syn, decay, x.w); e = fmaf(-syn, inv_tau, o.w); acc = fmaf(e, e, acc);
                }
            }

            __syncwarp();                       // all lanes done reading slot s
            if (ci + 2 < n_ci) issue(ci + 2);   // refill the slot just vacated
        }
    }

    // ===== tail / generic path: scalar thread-per-row from global =====
    if (T > 0) {
        for (long long row = fast_rows + (long long)blockIdx.x * BLK + tid;
             row < rows; row += (long long)GRID * BLK) {
            const float* tg = target  + row * (long long)T;
            const float* op = outputs + row * (long long)T;
            float syn = 0.0f;
            for (int t = 0; t < T; ++t) {
                syn = fmaf(syn, decay, tg[t]);
                const float e = fmaf(-syn, inv_tau, op[t]);
                acc = fmaf(e, e, acc);
            }
        }
    }

    // ---- block reduce ----
    #pragma unroll
    for (int off = 16; off > 0; off >>= 1)
        acc += __shfl_xor_sync(0xFFFFFFFF, acc, off);

    __shared__ float wsum[NWARP];
    if (lane == 0) wsum[wid] = acc;
    __syncthreads();

    __shared__ bool is_last;
    if (tid == 0) {
        float s = 0.0f;
        #pragma unroll
        for (int i = 0; i < NWARP; ++i) s += wsum[i];
        g_partials[blockIdx.x] = s;
        __threadfence();
        const unsigned prev = atomicInc(&g_tick, GRID - 1);   // wraps to 0 each launch
        is_last = (prev == GRID - 1);
    }
    __syncthreads();

    if (is_last) {
        double d = 0.0;
        for (int i = tid; i < GRID; i += BLK)
            d += (double)g_partials[i];
        #pragma unroll
        for (int off = 16; off > 0; off >>= 1)
            d += __shfl_xor_sync(0xFFFFFFFF, d, off);
        __shared__ double dsum[NWARP];
        if (lane == 0) dsum[wid] = d;
        __syncthreads();
        if (tid == 0) {
            double t = 0.0;
            #pragma unroll
            for (int i = 0; i < NWARP; ++i) t += dsum[i];
            out[0] = (float)(0.5 * t);
        }
    }
}

extern "C" void kernel_launch(void* const* d_in, const int* in_sizes, int n_in,
                              void* d_out, int out_size)
{
    const float* outputs = (const float*)d_in[0];
    const float* target  = (const float*)d_in[1];
    const int*   n_steps = (const int*)d_in[2];
    const int*   tau_s   = (const int*)d_in[3];
    float*       out     = (float*)d_out;

    const long long total = (long long)in_sizes[0];

    cudaFuncSetAttribute(spike_loss_kernel,
                         cudaFuncAttributeMaxDynamicSharedMemorySize, SMEM_BYTES);
    spike_loss_kernel<<<GRID, BLK, SMEM_BYTES>>>(outputs, target, n_steps, tau_s, total, out);
}